// round 1
// baseline (speedup 1.0000x reference)
#include <cuda_runtime.h>
#include <math.h>

// Problem constants
#define BATCH   2
#define SEQ     2048
#define DMODEL  2048
#define NH      16
#define NKV     8
#define HD      128
#define M_ROWS  (BATCH*SEQ)          // 4096
#define KV_D    (NKV*HD)             // 1024

// Scratch (allowed: __device__ globals, no runtime allocation)
__device__ float g_q  [(size_t)M_ROWS * DMODEL];   // [b*s, 16*128]
__device__ float g_k  [(size_t)M_ROWS * KV_D];     // [b*s,  8*128]
__device__ float g_v  [(size_t)M_ROWS * KV_D];
__device__ float g_att[(size_t)M_ROWS * DMODEL];   // attention out, [b*s, 16*128]

// ---------------------------------------------------------------------------
// SGEMM: C[M,N] = A[M,K] @ B[N,K]^T   (both operands K-contiguous, like x@W.T)
// BM=BN=128, BK=16, 256 threads, 8x8 microtile (split 4+4 rows/cols for
// conflict-free float4 smem reads), smem stride padded to 132.
// ---------------------------------------------------------------------------
__global__ __launch_bounds__(256)
void sgemm_tn(const float* __restrict__ A, const float* __restrict__ B,
              float* __restrict__ C, int M, int N, int K)
{
    __shared__ float As[16 * 132];
    __shared__ float Bs[16 * 132];

    const int tid = threadIdx.x;
    const int tx  = tid & 15;        // 0..15
    const int ty  = tid >> 4;        // 0..15
    const int m0  = blockIdx.y * 128;
    const int n0  = blockIdx.x * 128;

    const float* Ab = A + (size_t)m0 * K;
    const float* Bb = B + (size_t)n0 * K;

    float acc[8][8];
#pragma unroll
    for (int i = 0; i < 8; i++)
#pragma unroll
        for (int j = 0; j < 8; j++) acc[i][j] = 0.0f;

    for (int kt = 0; kt < K; kt += 16) {
        // Load A tile [128x16] and B tile [128x16], store transposed [16][132]
#pragma unroll
        for (int q = 0; q < 2; q++) {
            int f4  = tid + q * 256;     // 0..511
            int row = f4 >> 2;           // 0..127
            int c4  = f4 & 3;            // 0..3
            float4 va = *(const float4*)(Ab + (size_t)row * K + kt + c4 * 4);
            As[(c4*4+0)*132 + row] = va.x;
            As[(c4*4+1)*132 + row] = va.y;
            As[(c4*4+2)*132 + row] = va.z;
            As[(c4*4+3)*132 + row] = va.w;
            float4 vb = *(const float4*)(Bb + (size_t)row * K + kt + c4 * 4);
            Bs[(c4*4+0)*132 + row] = vb.x;
            Bs[(c4*4+1)*132 + row] = vb.y;
            Bs[(c4*4+2)*132 + row] = vb.z;
            Bs[(c4*4+3)*132 + row] = vb.w;
        }
        __syncthreads();

#pragma unroll
        for (int kk = 0; kk < 16; kk++) {
            float4 a0 = *(const float4*)&As[kk*132 + ty*4];
            float4 a1 = *(const float4*)&As[kk*132 + 64 + ty*4];
            float4 b0 = *(const float4*)&Bs[kk*132 + tx*4];
            float4 b1 = *(const float4*)&Bs[kk*132 + 64 + tx*4];
            float ar[8] = {a0.x,a0.y,a0.z,a0.w, a1.x,a1.y,a1.z,a1.w};
            float br[8] = {b0.x,b0.y,b0.z,b0.w, b1.x,b1.y,b1.z,b1.w};
#pragma unroll
            for (int i = 0; i < 8; i++)
#pragma unroll
                for (int j = 0; j < 8; j++)
                    acc[i][j] = fmaf(ar[i], br[j], acc[i][j]);
        }
        __syncthreads();
    }

    // Epilogue: rows {ty*4+i, 64+ty*4+i}, cols {n0+tx*4+j, n0+64+tx*4+j}
#pragma unroll
    for (int i = 0; i < 8; i++) {
        int row = m0 + ((i < 4) ? (ty*4 + i) : (64 + ty*4 + (i-4)));
        float* Crow = C + (size_t)row * N + n0;
        float4 c0 = make_float4(acc[i][0], acc[i][1], acc[i][2], acc[i][3]);
        float4 c1 = make_float4(acc[i][4], acc[i][5], acc[i][6], acc[i][7]);
        *(float4*)(Crow + tx*4)       = c0;
        *(float4*)(Crow + 64 + tx*4)  = c1;
    }
}

// ---------------------------------------------------------------------------
// RoPE (Gemma2): out[i] = x[i]*cos - x[i+64]*sin ; out[i+64] = x[i+64]*cos + x[i]*sin
// Grid: (b*s, NH+NKV) blocks, 64 threads. hh<NH -> q head, else k head.
// ---------------------------------------------------------------------------
__global__ __launch_bounds__(64)
void rope_kernel()
{
    const int m  = blockIdx.x;               // 0..4095
    const int hh = blockIdx.y;               // 0..23
    const int i  = threadIdx.x;              // 0..63
    const int pos = m & (SEQ - 1);

    // inv_freq = 10000^(-i/64) = 2^(-i * log2(10000)/64)
    const float L = 13.287712379549449f / 64.0f;
    float inv_freq = exp2f(-(float)i * L);
    float ang = (float)pos * inv_freq;
    float s, c;
    sincosf(ang, &s, &c);

    float* ptr = (hh < NH)
        ? (g_q + (size_t)m * DMODEL + hh * HD)
        : (g_k + (size_t)m * KV_D   + (hh - NH) * HD);

    float x1 = ptr[i];
    float x2 = ptr[i + 64];
    ptr[i]      = x1 * c - x2 * s;
    ptr[i + 64] = x2 * c + x1 * s;
}

// ---------------------------------------------------------------------------
// Flash attention with Gemma2 softcap + causal mask.
// BQ=BK=64, 256 threads (16x16). Thread (ty,tx):
//   S microtile: rows r_i = ty*4+i (i<4), cols c_j = tx + 16*j (j<4)
//   O microtile: rows r_i, dims {tx*4..+3} and {64+tx*4..+3}
// Scale (1/sqrt(128))/SOFTCAP folded into Q; score = tanhf(dot)*50.
// ---------------------------------------------------------------------------
#define ATT_SMEM_FLOATS (64*128 + 64*132 + 64*128 + 64*64)

__global__ __launch_bounds__(256)
void attn_kernel()
{
    extern __shared__ float sm[];
    float* Qs = sm;                    // [64][128]
    float* Ks = Qs + 64*128;           // [64][132]  (pad vs stride-128 bank clash)
    float* Vs = Ks + 64*132;           // [64][128]
    float* Ps = Vs + 64*128;           // [64][64]

    const int tid = threadIdx.x;
    const int tx  = tid & 15;
    const int ty  = tid >> 4;
    const int qt  = blockIdx.x;        // 0..31
    const int h   = blockIdx.y;        // 0..15
    const int bb  = blockIdx.z;        // 0..1
    const int kvh = h >> 1;

    const float* Qg = g_q + ((size_t)(bb*SEQ + qt*64)) * DMODEL + h * HD;
    const float* Kg = g_k + (size_t)(bb*SEQ) * KV_D + kvh * HD;
    const float* Vg = g_v + (size_t)(bb*SEQ) * KV_D + kvh * HD;

    const float qscale = 0.08838834764831845f / 50.0f;   // rsqrt(128)/SOFTCAP

    // Load Q tile (scaled)
#pragma unroll
    for (int t = 0; t < 8; t++) {
        int f4  = t*256 + tid;         // 0..2047
        int row = f4 >> 5;             // 0..63
        int c4  = f4 & 31;             // 0..31
        float4 v = *(const float4*)(Qg + (size_t)row * DMODEL + c4*4);
        v.x *= qscale; v.y *= qscale; v.z *= qscale; v.w *= qscale;
        *(float4*)&Qs[row*128 + c4*4] = v;
    }

    float m_i[4], l_i[4], o[4][8];
#pragma unroll
    for (int i = 0; i < 4; i++) {
        m_i[i] = -1e30f; l_i[i] = 0.0f;
#pragma unroll
        for (int e = 0; e < 8; e++) o[i][e] = 0.0f;
    }

    const int nkt = qt + 1;            // causal tiles
    for (int kt = 0; kt < nkt; kt++) {
        // Load K, V tiles
#pragma unroll
        for (int t = 0; t < 8; t++) {
            int f4  = t*256 + tid;
            int row = f4 >> 5;
            int c4  = f4 & 31;
            float4 kv = *(const float4*)(Kg + (size_t)(kt*64 + row) * KV_D + c4*4);
            *(float4*)&Ks[row*132 + c4*4] = kv;
            float4 vv = *(const float4*)(Vg + (size_t)(kt*64 + row) * KV_D + c4*4);
            *(float4*)&Vs[row*128 + c4*4] = vv;
        }
        __syncthreads();

        // S = Q @ K^T  (4x4 per thread)
        float sacc[4][4];
#pragma unroll
        for (int i = 0; i < 4; i++)
#pragma unroll
            for (int j = 0; j < 4; j++) sacc[i][j] = 0.0f;

#pragma unroll 4
        for (int d = 0; d < 128; d += 4) {
            float4 qf[4], kf[4];
#pragma unroll
            for (int i = 0; i < 4; i++) qf[i] = *(const float4*)&Qs[(ty*4+i)*128 + d];
#pragma unroll
            for (int j = 0; j < 4; j++) kf[j] = *(const float4*)&Ks[(tx + 16*j)*132 + d];
#pragma unroll
            for (int i = 0; i < 4; i++)
#pragma unroll
                for (int j = 0; j < 4; j++) {
                    sacc[i][j] = fmaf(qf[i].x, kf[j].x, sacc[i][j]);
                    sacc[i][j] = fmaf(qf[i].y, kf[j].y, sacc[i][j]);
                    sacc[i][j] = fmaf(qf[i].z, kf[j].z, sacc[i][j]);
                    sacc[i][j] = fmaf(qf[i].w, kf[j].w, sacc[i][j]);
                }
        }

        // Softcap + causal mask (diagonal tile only, tile-local indices)
        const bool diag = (kt == qt);
        float sc[4][4];
#pragma unroll
        for (int i = 0; i < 4; i++) {
            int qp = ty*4 + i;
#pragma unroll
            for (int j = 0; j < 4; j++) {
                float v = tanhf(sacc[i][j]) * 50.0f;
                if (diag && (tx + 16*j) > qp) v = -1e30f;
                sc[i][j] = v;
            }
        }

        // Online softmax update
        float p[4][4];
#pragma unroll
        for (int i = 0; i < 4; i++) {
            float rm = fmaxf(fmaxf(sc[i][0], sc[i][1]), fmaxf(sc[i][2], sc[i][3]));
#pragma unroll
            for (int off = 8; off >= 1; off >>= 1)
                rm = fmaxf(rm, __shfl_xor_sync(0xffffffffu, rm, off));
            float mnew = fmaxf(m_i[i], rm);
            float rs = 0.0f;
#pragma unroll
            for (int j = 0; j < 4; j++) {
                p[i][j] = __expf(sc[i][j] - mnew);
                rs += p[i][j];
            }
#pragma unroll
            for (int off = 8; off >= 1; off >>= 1)
                rs += __shfl_xor_sync(0xffffffffu, rs, off);
            float alpha = __expf(m_i[i] - mnew);
            l_i[i] = l_i[i] * alpha + rs;
            m_i[i] = mnew;
#pragma unroll
            for (int e = 0; e < 8; e++) o[i][e] *= alpha;
        }

        // Stage P to smem
#pragma unroll
        for (int i = 0; i < 4; i++)
#pragma unroll
            for (int j = 0; j < 4; j++)
                Ps[(ty*4+i)*64 + tx + 16*j] = p[i][j];
        __syncthreads();

        // O += P @ V
#pragma unroll 4
        for (int jj = 0; jj < 64; jj++) {
            float4 v0 = *(const float4*)&Vs[jj*128 + tx*4];
            float4 v1 = *(const float4*)&Vs[jj*128 + 64 + tx*4];
#pragma unroll
            for (int i = 0; i < 4; i++) {
                float pp = Ps[(ty*4+i)*64 + jj];
                o[i][0] = fmaf(pp, v0.x, o[i][0]);
                o[i][1] = fmaf(pp, v0.y, o[i][1]);
                o[i][2] = fmaf(pp, v0.z, o[i][2]);
                o[i][3] = fmaf(pp, v0.w, o[i][3]);
                o[i][4] = fmaf(pp, v1.x, o[i][4]);
                o[i][5] = fmaf(pp, v1.y, o[i][5]);
                o[i][6] = fmaf(pp, v1.z, o[i][6]);
                o[i][7] = fmaf(pp, v1.w, o[i][7]);
            }
        }
        __syncthreads();
    }

    // Normalize + write out (layout [b*s, 16*128])
#pragma unroll
    for (int i = 0; i < 4; i++) {
        float inv = 1.0f / l_i[i];
        int rowg = bb*SEQ + qt*64 + ty*4 + i;
        float* op = g_att + (size_t)rowg * DMODEL + h * HD;
        float4 c0 = make_float4(o[i][0]*inv, o[i][1]*inv, o[i][2]*inv, o[i][3]*inv);
        float4 c1 = make_float4(o[i][4]*inv, o[i][5]*inv, o[i][6]*inv, o[i][7]*inv);
        *(float4*)(op + tx*4)      = c0;
        *(float4*)(op + 64 + tx*4) = c1;
    }
}

// ---------------------------------------------------------------------------
extern "C" void kernel_launch(void* const* d_in, const int* in_sizes, int n_in,
                              void* d_out, int out_size)
{
    const float* x  = (const float*)d_in[0];
    const float* wq = (const float*)d_in[1];
    const float* wk = (const float*)d_in[2];
    const float* wv = (const float*)d_in[3];
    const float* wo = (const float*)d_in[4];
    float* out = (float*)d_out;

    float *gq, *gk, *gv, *ga;
    cudaGetSymbolAddress((void**)&gq, g_q);
    cudaGetSymbolAddress((void**)&gk, g_k);
    cudaGetSymbolAddress((void**)&gv, g_v);
    cudaGetSymbolAddress((void**)&ga, g_att);

    const size_t att_smem = (size_t)ATT_SMEM_FLOATS * sizeof(float);
    cudaFuncSetAttribute(attn_kernel,
                         cudaFuncAttributeMaxDynamicSharedMemorySize,
                         (int)att_smem);

    // QKV projections
    sgemm_tn<<<dim3(DMODEL/128, M_ROWS/128), 256>>>(x, wq, gq, M_ROWS, DMODEL, DMODEL);
    sgemm_tn<<<dim3(KV_D /128, M_ROWS/128), 256>>>(x, wk, gk, M_ROWS, KV_D,  DMODEL);
    sgemm_tn<<<dim3(KV_D /128, M_ROWS/128), 256>>>(x, wv, gv, M_ROWS, KV_D,  DMODEL);

    // RoPE on Q and K
    rope_kernel<<<dim3(M_ROWS, NH + NKV), 64>>>();

    // Flash attention
    attn_kernel<<<dim3(SEQ/64, NH, BATCH), 256, att_smem>>>();

    // Output projection
    sgemm_tn<<<dim3(DMODEL/128, M_ROWS/128), 256>>>(ga, wo, out, M_ROWS, DMODEL, DMODEL);
}

// round 4
// speedup vs baseline: 1.9024x; 1.9024x over previous
#include <cuda_runtime.h>
#include <math.h>
#include <cstdint>

// Problem constants
#define BATCH   2
#define SEQ     2048
#define DMODEL  2048
#define NH      16
#define NKV     8
#define HD      128
#define M_ROWS  (BATCH*SEQ)          // 4096
#define KV_D    (NKV*HD)             // 1024

// Scratch (allowed: __device__ globals)
__device__ float g_q  [(size_t)M_ROWS * DMODEL];
__device__ float g_k  [(size_t)M_ROWS * KV_D];
__device__ float g_v  [(size_t)M_ROWS * KV_D];
__device__ float g_att[(size_t)M_ROWS * DMODEL];
// tf32-rounded copies (HMMA truncates; pre-round to kill truncation bias)
__device__ float g_xc  [(size_t)M_ROWS * DMODEL];
__device__ float g_attc[(size_t)M_ROWS * DMODEL];
__device__ float g_wqc [(size_t)DMODEL * DMODEL];
__device__ float g_wkc [(size_t)KV_D   * DMODEL];
__device__ float g_wvc [(size_t)KV_D   * DMODEL];
__device__ float g_woc [(size_t)DMODEL * DMODEL];

// ============================================================================
// Helpers (baseline ISA only: mma.sync + cp.async, both sm_80+)
// ============================================================================
__device__ __forceinline__ uint32_t smem_u32(const void* p) {
    uint32_t a;
    asm("{ .reg .u64 t; cvta.to.shared.u64 t, %1; cvt.u32.u64 %0, t; }" : "=r"(a) : "l"(p));
    return a;
}
#define CP16(dst, src) \
    asm volatile("cp.async.cg.shared.global [%0], [%1], 16;" :: "r"(dst), "l"(src) : "memory")
#define CP_COMMIT() asm volatile("cp.async.commit_group;" ::: "memory")
#define CP_WAIT1()  asm volatile("cp.async.wait_group 1;" ::: "memory")
#define CP_WAIT0()  asm volatile("cp.async.wait_group 0;" ::: "memory")

__device__ __forceinline__ float to_tf32(float x) {
    float r; asm("cvt.rna.tf32.f32 %0, %1;" : "=f"(r) : "f"(x)); return r;
}

// ---------------------------------------------------------------------------
// Round-to-nearest tf32 conversion pass (float4 grid-stride-free, exact size)
// ---------------------------------------------------------------------------
__global__ __launch_bounds__(256)
void cvt_tf32_kernel(const float* __restrict__ in, float* __restrict__ out, int n4)
{
    int i = blockIdx.x * blockDim.x + threadIdx.x;
    if (i < n4) {
        float4 v = ((const float4*)in)[i];
        v.x = to_tf32(v.x); v.y = to_tf32(v.y);
        v.z = to_tf32(v.z); v.w = to_tf32(v.w);
        ((float4*)out)[i] = v;
    }
}

// ============================================================================
// tf32 mma.sync GEMM: C[M,N] = A[M,K] @ B[N,K]^T   (A,B already tf32-rounded)
// BM=BN=128, BK=32, 256 threads = 8 warps (2x4), warp tile 64x32,
// m16n8k8 fragments, cp.async double buffer, smem row stride 36 (pad).
// ============================================================================
#define BM 128
#define BN 128
#define BK 32
#define SROW 36
#define BUF_FLOATS ((BM + BN) * SROW)            // 9216 floats
#define GEMM_SMEM_BYTES (2 * BUF_FLOATS * 4)     // 73728 B

__global__ __launch_bounds__(256, 2)
void gemm_tf32_mma(const float* __restrict__ A, const float* __restrict__ B,
                   float* __restrict__ C, int M, int N, int K)
{
    extern __shared__ float sm[];

    const int tid  = threadIdx.x;
    const int lane = tid & 31;
    const int wid  = tid >> 5;
    const int wm   = wid >> 2;          // 0..1
    const int wn   = wid & 3;           // 0..3
    const int gr   = lane >> 2;         // 0..7
    const int tg   = lane & 3;          // 0..3

    const int m0 = blockIdx.y * BM;
    const int n0 = blockIdx.x * BN;

    // Loader mapping: 256 threads cover 32 rows x 8 float4-cols per pass, 4 passes.
    const int lr = tid >> 3;            // 0..31
    const int lc = tid & 7;             // 0..7

    const float* Ag = A + (size_t)(m0 + lr) * K + lc * 4;
    const float* Bg = B + (size_t)(n0 + lr) * K + lc * 4;

    const uint32_t sbase = smem_u32(sm);
    const uint32_t awr = sbase + (uint32_t)(lr * SROW + lc * 4) * 4;
    const uint32_t bwr = awr + (uint32_t)(BM * SROW) * 4;

    float acc[4][4][4];
#pragma unroll
    for (int i = 0; i < 4; i++)
#pragma unroll
        for (int j = 0; j < 4; j++)
#pragma unroll
            for (int e = 0; e < 4; e++) acc[i][j][e] = 0.0f;

    // Prologue: async-load chunk 0 into buffer 0
#pragma unroll
    for (int it = 0; it < 4; it++) {
        CP16(awr + (uint32_t)(it * 32 * SROW) * 4, Ag + (size_t)(it * 32) * K);
        CP16(bwr + (uint32_t)(it * 32 * SROW) * 4, Bg + (size_t)(it * 32) * K);
    }
    CP_COMMIT();

    const int NKT = K / BK;             // 64
    for (int kt = 0; kt < NKT; kt++) {
        const int buf = kt & 1;
        if (kt + 1 < NKT) {
            const uint32_t boff = (uint32_t)((buf ^ 1) * BUF_FLOATS) * 4;
            const float* Ag2 = Ag + (kt + 1) * BK;
            const float* Bg2 = Bg + (kt + 1) * BK;
#pragma unroll
            for (int it = 0; it < 4; it++) {
                CP16(awr + boff + (uint32_t)(it * 32 * SROW) * 4, Ag2 + (size_t)(it * 32) * K);
                CP16(bwr + boff + (uint32_t)(it * 32 * SROW) * 4, Bg2 + (size_t)(it * 32) * K);
            }
            CP_COMMIT();
            CP_WAIT1();
        } else {
            CP_WAIT0();
        }
        __syncthreads();

        const float* as_ = sm + buf * BUF_FLOATS;
        const float* bs_ = as_ + BM * SROW;

#pragma unroll
        for (int g = 0; g < 4; g++) {
            uint32_t af[4][4];
            uint32_t bf[4][2];
#pragma unroll
            for (int i = 0; i < 4; i++) {
                const float* rp = as_ + (wm * 64 + i * 16 + gr) * SROW + g * 8 + tg;
                af[i][0] = __float_as_uint(rp[0]);            // (row g,    k=t)
                af[i][1] = __float_as_uint(rp[8 * SROW]);     // (row g+8,  k=t)
                af[i][2] = __float_as_uint(rp[4]);            // (row g,    k=t+4)
                af[i][3] = __float_as_uint(rp[8 * SROW + 4]); // (row g+8,  k=t+4)
            }
#pragma unroll
            for (int j = 0; j < 4; j++) {
                const float* bp = bs_ + (wn * 32 + j * 8 + gr) * SROW + g * 8 + tg;
                bf[j][0] = __float_as_uint(bp[0]);            // (k=t,   n=gr)
                bf[j][1] = __float_as_uint(bp[4]);            // (k=t+4, n=gr)
            }
#pragma unroll
            for (int i = 0; i < 4; i++)
#pragma unroll
                for (int j = 0; j < 4; j++) {
                    asm volatile(
                        "mma.sync.aligned.m16n8k8.row.col.f32.tf32.tf32.f32 "
                        "{%0,%1,%2,%3}, {%4,%5,%6,%7}, {%8,%9}, {%0,%1,%2,%3};"
                        : "+f"(acc[i][j][0]), "+f"(acc[i][j][1]),
                          "+f"(acc[i][j][2]), "+f"(acc[i][j][3])
                        : "r"(af[i][0]), "r"(af[i][1]), "r"(af[i][2]), "r"(af[i][3]),
                          "r"(bf[j][0]), "r"(bf[j][1]));
                }
        }
        __syncthreads();
    }

    // Epilogue: c0,c1 = (row, 2t..2t+1); c2,c3 = (row+8, 2t..2t+1)
#pragma unroll
    for (int i = 0; i < 4; i++) {
        const int row = m0 + wm * 64 + i * 16 + gr;
#pragma unroll
        for (int j = 0; j < 4; j++) {
            const int coln = n0 + wn * 32 + j * 8 + tg * 2;
            *(float2*)(C + (size_t)row * N + coln) =
                make_float2(acc[i][j][0], acc[i][j][1]);
            *(float2*)(C + (size_t)(row + 8) * N + coln) =
                make_float2(acc[i][j][2], acc[i][j][3]);
        }
    }
}

// ---------------------------------------------------------------------------
// RoPE (Gemma2)
// ---------------------------------------------------------------------------
__global__ __launch_bounds__(64)
void rope_kernel()
{
    const int m  = blockIdx.x;
    const int hh = blockIdx.y;
    const int i  = threadIdx.x;
    const int pos = m & (SEQ - 1);

    const float L = 13.287712379549449f / 64.0f;
    float inv_freq = exp2f(-(float)i * L);
    float ang = (float)pos * inv_freq;
    float s, c;
    sincosf(ang, &s, &c);

    float* ptr = (hh < NH)
        ? (g_q + (size_t)m * DMODEL + hh * HD)
        : (g_k + (size_t)m * KV_D   + (hh - NH) * HD);

    float x1 = ptr[i];
    float x2 = ptr[i + 64];
    ptr[i]      = x1 * c - x2 * s;
    ptr[i + 64] = x2 * c + x1 * s;
}

// ---------------------------------------------------------------------------
// Flash attention, fp32 FFMA (R1 passing version, unchanged)
// ---------------------------------------------------------------------------
#define ATT_SMEM_FLOATS (64*128 + 64*132 + 64*128 + 64*64)

__global__ __launch_bounds__(256)
void attn_kernel()
{
    extern __shared__ float smf[];
    float* Qs = smf;
    float* Ks = Qs + 64*128;
    float* Vs = Ks + 64*132;
    float* Ps = Vs + 64*128;

    const int tid = threadIdx.x;
    const int tx  = tid & 15;
    const int ty  = tid >> 4;
    const int qt  = blockIdx.x;
    const int h   = blockIdx.y;
    const int bb  = blockIdx.z;
    const int kvh = h >> 1;

    const float* Qg = g_q + ((size_t)(bb*SEQ + qt*64)) * DMODEL + h * HD;
    const float* Kg = g_k + (size_t)(bb*SEQ) * KV_D + kvh * HD;
    const float* Vg = g_v + (size_t)(bb*SEQ) * KV_D + kvh * HD;

    const float qscale = 0.08838834764831845f / 50.0f;

#pragma unroll
    for (int t = 0; t < 8; t++) {
        int f4  = t*256 + tid;
        int row = f4 >> 5;
        int c4  = f4 & 31;
        float4 v = *(const float4*)(Qg + (size_t)row * DMODEL + c4*4);
        v.x *= qscale; v.y *= qscale; v.z *= qscale; v.w *= qscale;
        *(float4*)&Qs[row*128 + c4*4] = v;
    }

    float m_i[4], l_i[4], o[4][8];
#pragma unroll
    for (int i = 0; i < 4; i++) {
        m_i[i] = -1e30f; l_i[i] = 0.0f;
#pragma unroll
        for (int e = 0; e < 8; e++) o[i][e] = 0.0f;
    }

    const int nkt = qt + 1;
    for (int kt = 0; kt < nkt; kt++) {
#pragma unroll
        for (int t = 0; t < 8; t++) {
            int f4  = t*256 + tid;
            int row = f4 >> 5;
            int c4  = f4 & 31;
            float4 kv = *(const float4*)(Kg + (size_t)(kt*64 + row) * KV_D + c4*4);
            *(float4*)&Ks[row*132 + c4*4] = kv;
            float4 vv = *(const float4*)(Vg + (size_t)(kt*64 + row) * KV_D + c4*4);
            *(float4*)&Vs[row*128 + c4*4] = vv;
        }
        __syncthreads();

        float sacc[4][4];
#pragma unroll
        for (int i = 0; i < 4; i++)
#pragma unroll
            for (int j = 0; j < 4; j++) sacc[i][j] = 0.0f;

#pragma unroll 4
        for (int d = 0; d < 128; d += 4) {
            float4 qf[4], kf[4];
#pragma unroll
            for (int i = 0; i < 4; i++) qf[i] = *(const float4*)&Qs[(ty*4+i)*128 + d];
#pragma unroll
            for (int j = 0; j < 4; j++) kf[j] = *(const float4*)&Ks[(tx + 16*j)*132 + d];
#pragma unroll
            for (int i = 0; i < 4; i++)
#pragma unroll
                for (int j = 0; j < 4; j++) {
                    sacc[i][j] = fmaf(qf[i].x, kf[j].x, sacc[i][j]);
                    sacc[i][j] = fmaf(qf[i].y, kf[j].y, sacc[i][j]);
                    sacc[i][j] = fmaf(qf[i].z, kf[j].z, sacc[i][j]);
                    sacc[i][j] = fmaf(qf[i].w, kf[j].w, sacc[i][j]);
                }
        }

        const bool diag = (kt == qt);
        float sc[4][4];
#pragma unroll
        for (int i = 0; i < 4; i++) {
            int qp = ty*4 + i;
#pragma unroll
            for (int j = 0; j < 4; j++) {
                float v = tanhf(sacc[i][j]) * 50.0f;
                if (diag && (tx + 16*j) > qp) v = -1e30f;
                sc[i][j] = v;
            }
        }

        float p[4][4];
#pragma unroll
        for (int i = 0; i < 4; i++) {
            float rm = fmaxf(fmaxf(sc[i][0], sc[i][1]), fmaxf(sc[i][2], sc[i][3]));
#pragma unroll
            for (int off = 8; off >= 1; off >>= 1)
                rm = fmaxf(rm, __shfl_xor_sync(0xffffffffu, rm, off));
            float mnew = fmaxf(m_i[i], rm);
            float rs = 0.0f;
#pragma unroll
            for (int j = 0; j < 4; j++) {
                p[i][j] = __expf(sc[i][j] - mnew);
                rs += p[i][j];
            }
#pragma unroll
            for (int off = 8; off >= 1; off >>= 1)
                rs += __shfl_xor_sync(0xffffffffu, rs, off);
            float alpha = __expf(m_i[i] - mnew);
            l_i[i] = l_i[i] * alpha + rs;
            m_i[i] = mnew;
#pragma unroll
            for (int e = 0; e < 8; e++) o[i][e] *= alpha;
        }

#pragma unroll
        for (int i = 0; i < 4; i++)
#pragma unroll
            for (int j = 0; j < 4; j++)
                Ps[(ty*4+i)*64 + tx + 16*j] = p[i][j];
        __syncthreads();

#pragma unroll 4
        for (int jj = 0; jj < 64; jj++) {
            float4 v0 = *(const float4*)&Vs[jj*128 + tx*4];
            float4 v1 = *(const float4*)&Vs[jj*128 + 64 + tx*4];
#pragma unroll
            for (int i = 0; i < 4; i++) {
                float pp = Ps[(ty*4+i)*64 + jj];
                o[i][0] = fmaf(pp, v0.x, o[i][0]);
                o[i][1] = fmaf(pp, v0.y, o[i][1]);
                o[i][2] = fmaf(pp, v0.z, o[i][2]);
                o[i][3] = fmaf(pp, v0.w, o[i][3]);
                o[i][4] = fmaf(pp, v1.x, o[i][4]);
                o[i][5] = fmaf(pp, v1.y, o[i][5]);
                o[i][6] = fmaf(pp, v1.z, o[i][6]);
                o[i][7] = fmaf(pp, v1.w, o[i][7]);
            }
        }
        __syncthreads();
    }

#pragma unroll
    for (int i = 0; i < 4; i++) {
        float inv = 1.0f / l_i[i];
        int rowg = bb*SEQ + qt*64 + ty*4 + i;
        float* op = g_att + (size_t)rowg * DMODEL + h * HD;
        float4 c0 = make_float4(o[i][0]*inv, o[i][1]*inv, o[i][2]*inv, o[i][3]*inv);
        float4 c1 = make_float4(o[i][4]*inv, o[i][5]*inv, o[i][6]*inv, o[i][7]*inv);
        *(float4*)(op + tx*4)      = c0;
        *(float4*)(op + 64 + tx*4) = c1;
    }
}

// ---------------------------------------------------------------------------
extern "C" void kernel_launch(void* const* d_in, const int* in_sizes, int n_in,
                              void* d_out, int out_size)
{
    const float* x  = (const float*)d_in[0];
    const float* wq = (const float*)d_in[1];
    const float* wk = (const float*)d_in[2];
    const float* wv = (const float*)d_in[3];
    const float* wo = (const float*)d_in[4];
    float* out = (float*)d_out;

    float *gq, *gk, *gv, *ga;
    float *xc, *attc, *wqc, *wkc, *wvc, *woc;
    cudaGetSymbolAddress((void**)&gq,  g_q);
    cudaGetSymbolAddress((void**)&gk,  g_k);
    cudaGetSymbolAddress((void**)&gv,  g_v);
    cudaGetSymbolAddress((void**)&ga,  g_att);
    cudaGetSymbolAddress((void**)&xc,  g_xc);
    cudaGetSymbolAddress((void**)&attc,g_attc);
    cudaGetSymbolAddress((void**)&wqc, g_wqc);
    cudaGetSymbolAddress((void**)&wkc, g_wkc);
    cudaGetSymbolAddress((void**)&wvc, g_wvc);
    cudaGetSymbolAddress((void**)&woc, g_woc);

    const size_t att_smem = (size_t)ATT_SMEM_FLOATS * sizeof(float);
    cudaFuncSetAttribute(attn_kernel,
                         cudaFuncAttributeMaxDynamicSharedMemorySize, (int)att_smem);
    cudaFuncSetAttribute(gemm_tf32_mma,
                         cudaFuncAttributeMaxDynamicSharedMemorySize, GEMM_SMEM_BYTES);

    // tf32 round-to-nearest copies of GEMM inputs
    const int n4_x  = M_ROWS * DMODEL / 4;
    const int n4_wq = DMODEL * DMODEL / 4;
    const int n4_wk = KV_D   * DMODEL / 4;
    cvt_tf32_kernel<<<(n4_x  + 255)/256, 256>>>(x,  xc,  n4_x);
    cvt_tf32_kernel<<<(n4_wq + 255)/256, 256>>>(wq, wqc, n4_wq);
    cvt_tf32_kernel<<<(n4_wk + 255)/256, 256>>>(wk, wkc, n4_wk);
    cvt_tf32_kernel<<<(n4_wk + 255)/256, 256>>>(wv, wvc, n4_wk);
    cvt_tf32_kernel<<<(n4_wq + 255)/256, 256>>>(wo, woc, n4_wq);

    // QKV projections (tensor-core tf32 mma.sync)
    gemm_tf32_mma<<<dim3(DMODEL/BN, M_ROWS/BM), 256, GEMM_SMEM_BYTES>>>(xc, wqc, gq, M_ROWS, DMODEL, DMODEL);
    gemm_tf32_mma<<<dim3(KV_D /BN, M_ROWS/BM), 256, GEMM_SMEM_BYTES>>>(xc, wkc, gk, M_ROWS, KV_D,  DMODEL);
    gemm_tf32_mma<<<dim3(KV_D /BN, M_ROWS/BM), 256, GEMM_SMEM_BYTES>>>(xc, wvc, gv, M_ROWS, KV_D,  DMODEL);

    // RoPE on Q and K
    rope_kernel<<<dim3(M_ROWS, NH + NKV), 64>>>();

    // Flash attention (fp32)
    attn_kernel<<<dim3(SEQ/64, NH, BATCH), 256, att_smem>>>();

    // Output projection
    cvt_tf32_kernel<<<(n4_x + 255)/256, 256>>>(ga, attc, n4_x);
    gemm_tf32_mma<<<dim3(DMODEL/BN, M_ROWS/BM), 256, GEMM_SMEM_BYTES>>>(attc, woc, out, M_ROWS, DMODEL, DMODEL);
}

// round 6
// speedup vs baseline: 3.3313x; 1.7511x over previous
#include <cuda_runtime.h>
#include <math.h>
#include <cstdint>

// Problem constants
#define BATCH   2
#define SEQ     2048
#define DMODEL  2048
#define NH      16
#define NKV     8
#define HD      128
#define M_ROWS  (BATCH*SEQ)          // 4096
#define KV_D    (NKV*HD)             // 1024

// Scratch (allowed: __device__ globals)
__device__ __align__(256) float g_q  [(size_t)M_ROWS * DMODEL];
__device__ __align__(256) float g_k  [(size_t)M_ROWS * KV_D];
__device__ __align__(256) float g_v  [(size_t)M_ROWS * KV_D];
__device__ __align__(256) float g_att[(size_t)M_ROWS * DMODEL];
// tf32-rounded copies (HMMA truncates; pre-round to kill truncation bias)
__device__ __align__(256) float g_xc  [(size_t)M_ROWS * DMODEL];
__device__ __align__(256) float g_attc[(size_t)M_ROWS * DMODEL];
__device__ __align__(256) float g_wqc [(size_t)DMODEL * DMODEL];
__device__ __align__(256) float g_wkc [(size_t)KV_D   * DMODEL];
__device__ __align__(256) float g_wvc [(size_t)KV_D   * DMODEL];
__device__ __align__(256) float g_woc [(size_t)DMODEL * DMODEL];

// ============================================================================
// Helpers (baseline ISA only: mma.sync + cp.async, both sm_80+)
// ============================================================================
__device__ __forceinline__ uint32_t smem_u32(const void* p) {
    uint32_t a;
    asm("{ .reg .u64 t; cvta.to.shared.u64 t, %1; cvt.u32.u64 %0, t; }" : "=r"(a) : "l"(p));
    return a;
}
#define CP16(dst, src) \
    asm volatile("cp.async.cg.shared.global [%0], [%1], 16;" :: "r"(dst), "l"(src) : "memory")
#define CP_COMMIT() asm volatile("cp.async.commit_group;" ::: "memory")
#define CP_WAIT1()  asm volatile("cp.async.wait_group 1;" ::: "memory")
#define CP_WAIT0()  asm volatile("cp.async.wait_group 0;" ::: "memory")

__device__ __forceinline__ float to_tf32(float x) {
    float r; asm("cvt.rna.tf32.f32 %0, %1;" : "=f"(r) : "f"(x)); return r;
}

__device__ __forceinline__ void mma_tf32(float* c, const uint32_t* a, const uint32_t* b) {
    asm volatile(
        "mma.sync.aligned.m16n8k8.row.col.f32.tf32.tf32.f32 "
        "{%0,%1,%2,%3}, {%4,%5,%6,%7}, {%8,%9}, {%0,%1,%2,%3};"
        : "+f"(c[0]), "+f"(c[1]), "+f"(c[2]), "+f"(c[3])
        : "r"(a[0]), "r"(a[1]), "r"(a[2]), "r"(a[3]), "r"(b[0]), "r"(b[1]));
}

// ---------------------------------------------------------------------------
// Round-to-nearest tf32 conversion pass
// ---------------------------------------------------------------------------
__global__ __launch_bounds__(256)
void cvt_tf32_kernel(const float* __restrict__ in, float* __restrict__ out, int n4)
{
    int i = blockIdx.x * blockDim.x + threadIdx.x;
    if (i < n4) {
        float4 v = ((const float4*)in)[i];
        v.x = to_tf32(v.x); v.y = to_tf32(v.y);
        v.z = to_tf32(v.z); v.w = to_tf32(v.w);
        ((float4*)out)[i] = v;
    }
}

// ============================================================================
// tf32 mma.sync GEMM (unchanged from R4-passing version)
// ============================================================================
#define BM 128
#define BN 128
#define BK 32
#define SROW 36
#define BUF_FLOATS ((BM + BN) * SROW)
#define GEMM_SMEM_BYTES (2 * BUF_FLOATS * 4)

__global__ __launch_bounds__(256, 2)
void gemm_tf32_mma(const float* __restrict__ A, const float* __restrict__ B,
                   float* __restrict__ C, int M, int N, int K)
{
    extern __shared__ float sm[];

    const int tid  = threadIdx.x;
    const int lane = tid & 31;
    const int wid  = tid >> 5;
    const int wm   = wid >> 2;
    const int wn   = wid & 3;
    const int gr   = lane >> 2;
    const int tg   = lane & 3;

    const int m0 = blockIdx.y * BM;
    const int n0 = blockIdx.x * BN;

    const int lr = tid >> 3;
    const int lc = tid & 7;

    const float* Ag = A + (size_t)(m0 + lr) * K + lc * 4;
    const float* Bg = B + (size_t)(n0 + lr) * K + lc * 4;

    const uint32_t sbase = smem_u32(sm);
    const uint32_t awr = sbase + (uint32_t)(lr * SROW + lc * 4) * 4;
    const uint32_t bwr = awr + (uint32_t)(BM * SROW) * 4;

    float acc[4][4][4];
#pragma unroll
    for (int i = 0; i < 4; i++)
#pragma unroll
        for (int j = 0; j < 4; j++)
#pragma unroll
            for (int e = 0; e < 4; e++) acc[i][j][e] = 0.0f;

#pragma unroll
    for (int it = 0; it < 4; it++) {
        CP16(awr + (uint32_t)(it * 32 * SROW) * 4, Ag + (size_t)(it * 32) * K);
        CP16(bwr + (uint32_t)(it * 32 * SROW) * 4, Bg + (size_t)(it * 32) * K);
    }
    CP_COMMIT();

    const int NKT = K / BK;
    for (int kt = 0; kt < NKT; kt++) {
        const int buf = kt & 1;
        if (kt + 1 < NKT) {
            const uint32_t boff = (uint32_t)((buf ^ 1) * BUF_FLOATS) * 4;
            const float* Ag2 = Ag + (kt + 1) * BK;
            const float* Bg2 = Bg + (kt + 1) * BK;
#pragma unroll
            for (int it = 0; it < 4; it++) {
                CP16(awr + boff + (uint32_t)(it * 32 * SROW) * 4, Ag2 + (size_t)(it * 32) * K);
                CP16(bwr + boff + (uint32_t)(it * 32 * SROW) * 4, Bg2 + (size_t)(it * 32) * K);
            }
            CP_COMMIT();
            CP_WAIT1();
        } else {
            CP_WAIT0();
        }
        __syncthreads();

        const float* as_ = sm + buf * BUF_FLOATS;
        const float* bs_ = as_ + BM * SROW;

#pragma unroll
        for (int g = 0; g < 4; g++) {
            uint32_t af[4][4];
            uint32_t bf[4][2];
#pragma unroll
            for (int i = 0; i < 4; i++) {
                const float* rp = as_ + (wm * 64 + i * 16 + gr) * SROW + g * 8 + tg;
                af[i][0] = __float_as_uint(rp[0]);
                af[i][1] = __float_as_uint(rp[8 * SROW]);
                af[i][2] = __float_as_uint(rp[4]);
                af[i][3] = __float_as_uint(rp[8 * SROW + 4]);
            }
#pragma unroll
            for (int j = 0; j < 4; j++) {
                const float* bp = bs_ + (wn * 32 + j * 8 + gr) * SROW + g * 8 + tg;
                bf[j][0] = __float_as_uint(bp[0]);
                bf[j][1] = __float_as_uint(bp[4]);
            }
#pragma unroll
            for (int i = 0; i < 4; i++)
#pragma unroll
                for (int j = 0; j < 4; j++)
                    mma_tf32(acc[i][j], af[i], bf[j]);
        }
        __syncthreads();
    }

#pragma unroll
    for (int i = 0; i < 4; i++) {
        const int row = m0 + wm * 64 + i * 16 + gr;
#pragma unroll
        for (int j = 0; j < 4; j++) {
            const int coln = n0 + wn * 32 + j * 8 + tg * 2;
            *(float2*)(C + (size_t)row * N + coln) =
                make_float2(acc[i][j][0], acc[i][j][1]);
            *(float2*)(C + (size_t)(row + 8) * N + coln) =
                make_float2(acc[i][j][2], acc[i][j][3]);
        }
    }
}

// ---------------------------------------------------------------------------
// RoPE (Gemma2), now emits RN-tf32 values; Q additionally pre-scaled by
// rsqrt(128)/SOFTCAP so attention mma operands are rounding-clean.
// ---------------------------------------------------------------------------
__global__ __launch_bounds__(64)
void rope_kernel()
{
    const int m  = blockIdx.x;
    const int hh = blockIdx.y;
    const int i  = threadIdx.x;
    const int pos = m & (SEQ - 1);

    const float L = 13.287712379549449f / 64.0f;
    float inv_freq = exp2f(-(float)i * L);
    float ang = (float)pos * inv_freq;
    float s, c;
    sincosf(ang, &s, &c);

    const bool isq = (hh < NH);
    float* ptr = isq
        ? (g_q + (size_t)m * DMODEL + hh * HD)
        : (g_k + (size_t)m * KV_D   + (hh - NH) * HD);
    const float scl = isq ? (0.08838834764831845f / 50.0f) : 1.0f;

    float x1 = ptr[i];
    float x2 = ptr[i + 64];
    ptr[i]      = to_tf32((x1 * c - x2 * s) * scl);
    ptr[i + 64] = to_tf32((x2 * c + x1 * s) * scl);
}

// ============================================================================
// Tensor-core flash attention: 64x64 tiles, 4 warps, m16n8k8 tf32.
// Warp w owns q rows [w*16, w*16+16). Q fragments resident in registers.
// smem strides chosen for conflict-free fragment LDS:
//   Ks stride 132 -> (4gr+tg) bijective; Vs 136 -> (8tg+gr); Ps 68 -> (4gr+tg)
// ============================================================================
#define SK 132
#define SV 136
#define SP 68
#define ATT2_FLOATS (64*SK + 64*SV + 64*SP)
#define ATT2_SMEM_BYTES (ATT2_FLOATS * 4)       // 86016

__global__ __launch_bounds__(128, 2)
void attn_mma_kernel()
{
    extern __shared__ float sm[];
    float* Ks = sm;
    float* Vs = Ks + 64 * SK;
    float* Ps = Vs + 64 * SV;

    const int tid  = threadIdx.x;
    const int lane = tid & 31;
    const int w    = tid >> 5;          // 0..3
    const int gr   = lane >> 2;         // 0..7
    const int tg   = lane & 3;          // 0..3

    const int qt  = (int)gridDim.x - 1 - (int)blockIdx.x;   // big tiles first
    const int h   = blockIdx.y;
    const int bb  = blockIdx.z;
    const int kvh = h >> 1;

    const float* Qg = g_q + ((size_t)(bb*SEQ + qt*64)) * DMODEL + h * HD;
    const float* Kg = g_k + (size_t)(bb*SEQ) * KV_D + kvh * HD;
    const float* Vg = g_v + (size_t)(bb*SEQ) * KV_D + kvh * HD;

    const uint32_t ks_a = smem_u32(Ks);
    const uint32_t vs_a = smem_u32(Vs);

    // ---- Stage Q tile through Ks area, pull fragments into registers ----
#pragma unroll
    for (int p = 0; p < 16; p++) {
        int idx = p * 128 + tid;        // 0..2047 (64 rows x 32 x16B)
        int row = idx >> 5;
        int c16 = idx & 31;
        CP16(ks_a + (uint32_t)(row * SK + c16 * 4) * 4,
             Qg + (size_t)row * DMODEL + c16 * 4);
    }
    CP_COMMIT(); CP_WAIT0();
    __syncthreads();

    uint32_t qa[16][4];
#pragma unroll
    for (int kc = 0; kc < 16; kc++) {
        const float* rp = Ks + (w * 16 + gr) * SK + kc * 8 + tg;
        qa[kc][0] = __float_as_uint(rp[0]);
        qa[kc][1] = __float_as_uint(rp[8 * SK]);
        qa[kc][2] = __float_as_uint(rp[4]);
        qa[kc][3] = __float_as_uint(rp[8 * SK + 4]);
    }
    __syncthreads();

    float m0 = -1e30f, m1 = -1e30f, l0 = 0.0f, l1 = 0.0f;
    float co[16][4];
#pragma unroll
    for (int jb = 0; jb < 16; jb++)
#pragma unroll
        for (int e = 0; e < 4; e++) co[jb][e] = 0.0f;

    const int r0loc = w * 16 + gr;      // tile-local q rows
    const int r1loc = r0loc + 8;

    const int nkt = qt + 1;
    for (int kt = 0; kt < nkt; kt++) {
        // ---- load K,V tiles (already tf32-rounded in gmem) ----
#pragma unroll
        for (int p = 0; p < 16; p++) {
            int idx = p * 128 + tid;
            int row = idx >> 5;
            int c16 = idx & 31;
            const size_t goff = (size_t)(kt * 64 + row) * KV_D + c16 * 4;
            CP16(ks_a + (uint32_t)(row * SK + c16 * 4) * 4, Kg + goff);
            CP16(vs_a + (uint32_t)(row * SV + c16 * 4) * 4, Vg + goff);
        }
        CP_COMMIT(); CP_WAIT0();
        __syncthreads();

        // ---- S = Q @ K^T ----
        float sacc[8][4];
#pragma unroll
        for (int nb = 0; nb < 8; nb++)
#pragma unroll
            for (int e = 0; e < 4; e++) sacc[nb][e] = 0.0f;

#pragma unroll
        for (int kc = 0; kc < 16; kc++) {
            uint32_t bf[8][2];
#pragma unroll
            for (int nb = 0; nb < 8; nb++) {
                const float* bp = Ks + (nb * 8 + gr) * SK + kc * 8 + tg;
                bf[nb][0] = __float_as_uint(bp[0]);
                bf[nb][1] = __float_as_uint(bp[4]);
            }
#pragma unroll
            for (int nb = 0; nb < 8; nb++)
                mma_tf32(sacc[nb], qa[kc], bf[nb]);
        }

        // ---- softcap + causal mask ----
        const bool diag = (kt == qt);
#pragma unroll
        for (int nb = 0; nb < 8; nb++) {
#pragma unroll
            for (int e = 0; e < 4; e++) {
                float v = sacc[nb][e];
                float t = __expf(2.0f * v);
                float sc = __fdividef(t - 1.0f, t + 1.0f) * 50.0f;
                if (diag) {
                    int cloc = nb * 8 + 2 * tg + (e & 1);
                    int rloc = (e < 2) ? r0loc : r1loc;
                    if (cloc > rloc) sc = -1e30f;
                }
                sacc[nb][e] = sc;
            }
        }

        // ---- online softmax (rows r0, r1; quad reduction over tg) ----
        float rm0 = -1e30f, rm1 = -1e30f;
#pragma unroll
        for (int nb = 0; nb < 8; nb++) {
            rm0 = fmaxf(rm0, fmaxf(sacc[nb][0], sacc[nb][1]));
            rm1 = fmaxf(rm1, fmaxf(sacc[nb][2], sacc[nb][3]));
        }
#pragma unroll
        for (int off = 1; off <= 2; off <<= 1) {
            rm0 = fmaxf(rm0, __shfl_xor_sync(0xffffffffu, rm0, off));
            rm1 = fmaxf(rm1, __shfl_xor_sync(0xffffffffu, rm1, off));
        }
        const float mn0 = fmaxf(m0, rm0);
        const float mn1 = fmaxf(m1, rm1);

        float rs0 = 0.0f, rs1 = 0.0f;
#pragma unroll
        for (int nb = 0; nb < 8; nb++) {
            float p00 = to_tf32(__expf(sacc[nb][0] - mn0));
            float p01 = to_tf32(__expf(sacc[nb][1] - mn0));
            float p10 = to_tf32(__expf(sacc[nb][2] - mn1));
            float p11 = to_tf32(__expf(sacc[nb][3] - mn1));
            rs0 += p00 + p01;
            rs1 += p10 + p11;
            // stage P (own rows only; consumed by own warp after __syncwarp)
            *(float2*)&Ps[r0loc * SP + nb * 8 + 2 * tg] = make_float2(p00, p01);
            *(float2*)&Ps[r1loc * SP + nb * 8 + 2 * tg] = make_float2(p10, p11);
        }
#pragma unroll
        for (int off = 1; off <= 2; off <<= 1) {
            rs0 += __shfl_xor_sync(0xffffffffu, rs0, off);
            rs1 += __shfl_xor_sync(0xffffffffu, rs1, off);
        }
        const float a0 = __expf(m0 - mn0);
        const float a1 = __expf(m1 - mn1);
        l0 = l0 * a0 + rs0;  m0 = mn0;
        l1 = l1 * a1 + rs1;  m1 = mn1;
#pragma unroll
        for (int jb = 0; jb < 16; jb++) {
            co[jb][0] *= a0; co[jb][1] *= a0;
            co[jb][2] *= a1; co[jb][3] *= a1;
        }
        __syncwarp();

        // ---- O += P @ V ----
#pragma unroll
        for (int kc = 0; kc < 8; kc++) {
            uint32_t pa[4];
            const float* pp = Ps + r0loc * SP + kc * 8 + tg;
            pa[0] = __float_as_uint(pp[0]);
            pa[1] = __float_as_uint(pp[8 * SP]);
            pa[2] = __float_as_uint(pp[4]);
            pa[3] = __float_as_uint(pp[8 * SP + 4]);
#pragma unroll
            for (int jb = 0; jb < 16; jb++) {
                uint32_t bv[2];
                const float* vp = Vs + (kc * 8 + tg) * SV + jb * 8 + gr;
                bv[0] = __float_as_uint(vp[0]);
                bv[1] = __float_as_uint(vp[4 * SV]);
                mma_tf32(co[jb], pa, bv);
            }
        }
        __syncthreads();
    }

    // ---- normalize + write out ----
    const float inv0 = 1.0f / l0;
    const float inv1 = 1.0f / l1;
    const int rowg0 = bb * SEQ + qt * 64 + r0loc;
    float* op0 = g_att + (size_t)rowg0 * DMODEL + h * HD;
    float* op1 = g_att + (size_t)(rowg0 + 8) * DMODEL + h * HD;
#pragma unroll
    for (int jb = 0; jb < 16; jb++) {
        int col = jb * 8 + 2 * tg;
        *(float2*)(op0 + col) = make_float2(co[jb][0] * inv0, co[jb][1] * inv0);
        *(float2*)(op1 + col) = make_float2(co[jb][2] * inv1, co[jb][3] * inv1);
    }
}

// ---------------------------------------------------------------------------
extern "C" void kernel_launch(void* const* d_in, const int* in_sizes, int n_in,
                              void* d_out, int out_size)
{
    const float* x  = (const float*)d_in[0];
    const float* wq = (const float*)d_in[1];
    const float* wk = (const float*)d_in[2];
    const float* wv = (const float*)d_in[3];
    const float* wo = (const float*)d_in[4];
    float* out = (float*)d_out;

    float *gq, *gk, *gv, *ga;
    float *xc, *attc, *wqc, *wkc, *wvc, *woc;
    cudaGetSymbolAddress((void**)&gq,  g_q);
    cudaGetSymbolAddress((void**)&gk,  g_k);
    cudaGetSymbolAddress((void**)&gv,  g_v);
    cudaGetSymbolAddress((void**)&ga,  g_att);
    cudaGetSymbolAddress((void**)&xc,  g_xc);
    cudaGetSymbolAddress((void**)&attc,g_attc);
    cudaGetSymbolAddress((void**)&wqc, g_wqc);
    cudaGetSymbolAddress((void**)&wkc, g_wkc);
    cudaGetSymbolAddress((void**)&wvc, g_wvc);
    cudaGetSymbolAddress((void**)&woc, g_woc);

    cudaFuncSetAttribute(gemm_tf32_mma,
                         cudaFuncAttributeMaxDynamicSharedMemorySize, GEMM_SMEM_BYTES);
    cudaFuncSetAttribute(attn_mma_kernel,
                         cudaFuncAttributeMaxDynamicSharedMemorySize, ATT2_SMEM_BYTES);

    // tf32 round-to-nearest copies of GEMM inputs
    const int n4_x  = M_ROWS * DMODEL / 4;
    const int n4_wq = DMODEL * DMODEL / 4;
    const int n4_wk = KV_D   * DMODEL / 4;
    const int n4_v  = M_ROWS * KV_D   / 4;
    cvt_tf32_kernel<<<(n4_x  + 255)/256, 256>>>(x,  xc,  n4_x);
    cvt_tf32_kernel<<<(n4_wq + 255)/256, 256>>>(wq, wqc, n4_wq);
    cvt_tf32_kernel<<<(n4_wk + 255)/256, 256>>>(wk, wkc, n4_wk);
    cvt_tf32_kernel<<<(n4_wk + 255)/256, 256>>>(wv, wvc, n4_wk);
    cvt_tf32_kernel<<<(n4_wq + 255)/256, 256>>>(wo, woc, n4_wq);

    // QKV projections (tensor-core tf32 mma.sync)
    gemm_tf32_mma<<<dim3(DMODEL/BN, M_ROWS/BM), 256, GEMM_SMEM_BYTES>>>(xc, wqc, gq, M_ROWS, DMODEL, DMODEL);
    gemm_tf32_mma<<<dim3(KV_D /BN, M_ROWS/BM), 256, GEMM_SMEM_BYTES>>>(xc, wkc, gk, M_ROWS, KV_D,  DMODEL);
    gemm_tf32_mma<<<dim3(KV_D /BN, M_ROWS/BM), 256, GEMM_SMEM_BYTES>>>(xc, wvc, gv, M_ROWS, KV_D,  DMODEL);

    // RoPE (emits tf32-rounded Q(scaled)/K); V rounded in place
    rope_kernel<<<dim3(M_ROWS, NH + NKV), 64>>>();
    cvt_tf32_kernel<<<(n4_v + 255)/256, 256>>>(gv, gv, n4_v);

    // Tensor-core flash attention
    attn_mma_kernel<<<dim3(SEQ/64, NH, BATCH), 128, ATT2_SMEM_BYTES>>>();

    // Output projection
    cvt_tf32_kernel<<<(n4_x + 255)/256, 256>>>(ga, attc, n4_x);
    gemm_tf32_mma<<<dim3(DMODEL/BN, M_ROWS/BM), 256, GEMM_SMEM_BYTES>>>(attc, woc, out, M_ROWS, DMODEL, DMODEL);
}

// round 7
// speedup vs baseline: 3.4052x; 1.0222x over previous
#include <cuda_runtime.h>
#include <math.h>
#include <cstdint>

// Problem constants
#define BATCH   2
#define SEQ     2048
#define DMODEL  2048
#define NH      16
#define NKV     8
#define HD      128
#define M_ROWS  (BATCH*SEQ)          // 4096
#define KV_D    (NKV*HD)             // 1024

// Scratch (allowed: __device__ globals)
__device__ __align__(256) float g_q  [(size_t)M_ROWS * DMODEL];
__device__ __align__(256) float g_k  [(size_t)M_ROWS * KV_D];
__device__ __align__(256) float g_v  [(size_t)M_ROWS * KV_D];
__device__ __align__(256) float g_att[(size_t)M_ROWS * DMODEL];
// tf32-rounded copies (HMMA truncates; pre-round to kill truncation bias)
__device__ __align__(256) float g_xc  [(size_t)M_ROWS * DMODEL];
__device__ __align__(256) float g_wqc [(size_t)DMODEL * DMODEL];
__device__ __align__(256) float g_wkc [(size_t)KV_D   * DMODEL];
__device__ __align__(256) float g_wvc [(size_t)KV_D   * DMODEL];
__device__ __align__(256) float g_woc [(size_t)DMODEL * DMODEL];

// ============================================================================
// Helpers (baseline ISA only: mma.sync + cp.async, both sm_80+)
// ============================================================================
__device__ __forceinline__ uint32_t smem_u32(const void* p) {
    uint32_t a;
    asm("{ .reg .u64 t; cvta.to.shared.u64 t, %1; cvt.u32.u64 %0, t; }" : "=r"(a) : "l"(p));
    return a;
}
#define CP16(dst, src) \
    asm volatile("cp.async.cg.shared.global [%0], [%1], 16;" :: "r"(dst), "l"(src) : "memory")
#define CP_COMMIT() asm volatile("cp.async.commit_group;" ::: "memory")
#define CP_WAIT1()  asm volatile("cp.async.wait_group 1;" ::: "memory")
#define CP_WAIT0()  asm volatile("cp.async.wait_group 0;" ::: "memory")

__device__ __forceinline__ float to_tf32(float x) {
    float r; asm("cvt.rna.tf32.f32 %0, %1;" : "=f"(r) : "f"(x)); return r;
}

__device__ __forceinline__ void mma_tf32(float* c, const uint32_t* a, const uint32_t* b) {
    asm volatile(
        "mma.sync.aligned.m16n8k8.row.col.f32.tf32.tf32.f32 "
        "{%0,%1,%2,%3}, {%4,%5,%6,%7}, {%8,%9}, {%0,%1,%2,%3};"
        : "+f"(c[0]), "+f"(c[1]), "+f"(c[2]), "+f"(c[3])
        : "r"(a[0]), "r"(a[1]), "r"(a[2]), "r"(a[3]), "r"(b[0]), "r"(b[1]));
}

// ---------------------------------------------------------------------------
// Round-to-nearest tf32 conversion pass
// ---------------------------------------------------------------------------
__global__ __launch_bounds__(256)
void cvt_tf32_kernel(const float* __restrict__ in, float* __restrict__ out, int n4)
{
    int i = blockIdx.x * blockDim.x + threadIdx.x;
    if (i < n4) {
        float4 v = ((const float4*)in)[i];
        v.x = to_tf32(v.x); v.y = to_tf32(v.y);
        v.z = to_tf32(v.z); v.w = to_tf32(v.w);
        ((float4*)out)[i] = v;
    }
}

// ============================================================================
// tf32 mma.sync GEMM core (shared by fused-QKV and O-proj kernels)
// BM=BN=128, BK=32, 256 threads, cp.async double buffer, SROW=36 pad.
// Optional RN-tf32 rounding of the output (for V, consumed by attention mma).
// ============================================================================
#define BM 128
#define BN 128
#define BK 32
#define SROW 36
#define BUF_FLOATS ((BM + BN) * SROW)
#define GEMM_SMEM_BYTES (2 * BUF_FLOATS * 4)

__device__ __forceinline__
void gemm_core(const float* __restrict__ A, const float* __restrict__ B,
               float* __restrict__ C, int N, int K, int m0, int n0,
               bool rnd, float* sm)
{
    const int tid  = threadIdx.x;
    const int lane = tid & 31;
    const int wid  = tid >> 5;
    const int wm   = wid >> 2;
    const int wn   = wid & 3;
    const int gr   = lane >> 2;
    const int tg   = lane & 3;

    const int lr = tid >> 3;
    const int lc = tid & 7;

    const float* Ag = A + (size_t)(m0 + lr) * K + lc * 4;
    const float* Bg = B + (size_t)(n0 + lr) * K + lc * 4;

    const uint32_t sbase = smem_u32(sm);
    const uint32_t awr = sbase + (uint32_t)(lr * SROW + lc * 4) * 4;
    const uint32_t bwr = awr + (uint32_t)(BM * SROW) * 4;

    float acc[4][4][4];
#pragma unroll
    for (int i = 0; i < 4; i++)
#pragma unroll
        for (int j = 0; j < 4; j++)
#pragma unroll
            for (int e = 0; e < 4; e++) acc[i][j][e] = 0.0f;

#pragma unroll
    for (int it = 0; it < 4; it++) {
        CP16(awr + (uint32_t)(it * 32 * SROW) * 4, Ag + (size_t)(it * 32) * K);
        CP16(bwr + (uint32_t)(it * 32 * SROW) * 4, Bg + (size_t)(it * 32) * K);
    }
    CP_COMMIT();

    const int NKT = K / BK;
    for (int kt = 0; kt < NKT; kt++) {
        const int buf = kt & 1;
        if (kt + 1 < NKT) {
            const uint32_t boff = (uint32_t)((buf ^ 1) * BUF_FLOATS) * 4;
            const float* Ag2 = Ag + (kt + 1) * BK;
            const float* Bg2 = Bg + (kt + 1) * BK;
#pragma unroll
            for (int it = 0; it < 4; it++) {
                CP16(awr + boff + (uint32_t)(it * 32 * SROW) * 4, Ag2 + (size_t)(it * 32) * K);
                CP16(bwr + boff + (uint32_t)(it * 32 * SROW) * 4, Bg2 + (size_t)(it * 32) * K);
            }
            CP_COMMIT();
            CP_WAIT1();
        } else {
            CP_WAIT0();
        }
        __syncthreads();

        const float* as_ = sm + buf * BUF_FLOATS;
        const float* bs_ = as_ + BM * SROW;

#pragma unroll
        for (int g = 0; g < 4; g++) {
            uint32_t af[4][4];
            uint32_t bf[4][2];
#pragma unroll
            for (int i = 0; i < 4; i++) {
                const float* rp = as_ + (wm * 64 + i * 16 + gr) * SROW + g * 8 + tg;
                af[i][0] = __float_as_uint(rp[0]);
                af[i][1] = __float_as_uint(rp[8 * SROW]);
                af[i][2] = __float_as_uint(rp[4]);
                af[i][3] = __float_as_uint(rp[8 * SROW + 4]);
            }
#pragma unroll
            for (int j = 0; j < 4; j++) {
                const float* bp = bs_ + (wn * 32 + j * 8 + gr) * SROW + g * 8 + tg;
                bf[j][0] = __float_as_uint(bp[0]);
                bf[j][1] = __float_as_uint(bp[4]);
            }
#pragma unroll
            for (int i = 0; i < 4; i++)
#pragma unroll
                for (int j = 0; j < 4; j++)
                    mma_tf32(acc[i][j], af[i], bf[j]);
        }
        __syncthreads();
    }

#pragma unroll
    for (int i = 0; i < 4; i++) {
        const int row = m0 + wm * 64 + i * 16 + gr;
#pragma unroll
        for (int j = 0; j < 4; j++) {
            const int coln = n0 + wn * 32 + j * 8 + tg * 2;
            float c0 = acc[i][j][0], c1 = acc[i][j][1];
            float c2 = acc[i][j][2], c3 = acc[i][j][3];
            if (rnd) {
                c0 = to_tf32(c0); c1 = to_tf32(c1);
                c2 = to_tf32(c2); c3 = to_tf32(c3);
            }
            *(float2*)(C + (size_t)row * N + coln)       = make_float2(c0, c1);
            *(float2*)(C + (size_t)(row + 8) * N + coln) = make_float2(c2, c3);
        }
    }
}

// Fused QKV: x-blocks [0,16) -> Q, [16,24) -> K, [24,32) -> V (V output rounded)
__global__ __launch_bounds__(256, 2)
void gemm_qkv(const float* __restrict__ xc,
              const float* __restrict__ wq, const float* __restrict__ wk,
              const float* __restrict__ wv)
{
    extern __shared__ float sm[];
    const int xb = blockIdx.x;
    const int m0 = blockIdx.y * BM;

    const float* Bp;
    float* Cp;
    int N, n0;
    bool rnd = false;
    if (xb < 16)      { Bp = wq; Cp = g_q; N = DMODEL; n0 = xb * BN; }
    else if (xb < 24) { Bp = wk; Cp = g_k; N = KV_D;   n0 = (xb - 16) * BN; }
    else              { Bp = wv; Cp = g_v; N = KV_D;   n0 = (xb - 24) * BN; rnd = true; }

    gemm_core(xc, Bp, Cp, N, DMODEL, m0, n0, rnd, sm);
}

// Output projection: g_att (already tf32-rounded) @ wo^T -> out
__global__ __launch_bounds__(256, 2)
void gemm_o(const float* __restrict__ wo, float* __restrict__ out)
{
    extern __shared__ float sm[];
    gemm_core(g_att, wo, out, DMODEL, DMODEL, blockIdx.y * BM, blockIdx.x * BN,
              false, sm);
}

// ---------------------------------------------------------------------------
// RoPE (Gemma2), flattened indexing; emits RN-tf32, Q pre-scaled.
// t = (hh<<18) | (m<<6) | i
// ---------------------------------------------------------------------------
__global__ __launch_bounds__(256)
void rope_kernel()
{
    const int t  = blockIdx.x * 256 + threadIdx.x;
    const int i  = t & 63;
    const int m  = (t >> 6) & (M_ROWS - 1);
    const int hh = t >> 18;                 // 0..23
    const int pos = m & (SEQ - 1);

    const float L = 13.287712379549449f / 64.0f;
    float inv_freq = exp2f(-(float)i * L);
    float ang = (float)pos * inv_freq;
    float s, c;
    sincosf(ang, &s, &c);

    const bool isq = (hh < NH);
    float* ptr = isq
        ? (g_q + (size_t)m * DMODEL + hh * HD)
        : (g_k + (size_t)m * KV_D   + (hh - NH) * HD);
    const float scl = isq ? (0.08838834764831845f / 50.0f) : 1.0f;

    float x1 = ptr[i];
    float x2 = ptr[i + 64];
    ptr[i]      = to_tf32((x1 * c - x2 * s) * scl);
    ptr[i + 64] = to_tf32((x2 * c + x1 * s) * scl);
}

// ============================================================================
// Tensor-core flash attention: 64x64 tiles, 4 warps, m16n8k8 tf32.
// K and V in separate cp.async groups: V latency hidden behind S compute.
// Epilogue emits RN-tf32 (feeds O-proj HMMA directly).
// ============================================================================
#define SKA 132
#define SVA 136
#define SPA 68
#define ATT2_FLOATS (64*SKA + 64*SVA + 64*SPA)
#define ATT2_SMEM_BYTES (ATT2_FLOATS * 4)       // 86016

__global__ __launch_bounds__(128, 2)
void attn_mma_kernel()
{
    extern __shared__ float sm[];
    float* Ks = sm;
    float* Vs = Ks + 64 * SKA;
    float* Ps = Vs + 64 * SVA;

    const int tid  = threadIdx.x;
    const int lane = tid & 31;
    const int w    = tid >> 5;
    const int gr   = lane >> 2;
    const int tg   = lane & 3;

    const int qt  = (int)gridDim.x - 1 - (int)blockIdx.x;   // big tiles first
    const int h   = blockIdx.y;
    const int bb  = blockIdx.z;
    const int kvh = h >> 1;

    const float* Qg = g_q + ((size_t)(bb*SEQ + qt*64)) * DMODEL + h * HD;
    const float* Kg = g_k + (size_t)(bb*SEQ) * KV_D + kvh * HD;
    const float* Vg = g_v + (size_t)(bb*SEQ) * KV_D + kvh * HD;

    const uint32_t ks_a = smem_u32(Ks);
    const uint32_t vs_a = smem_u32(Vs);

    // ---- Stage Q tile through Ks area, pull fragments into registers ----
#pragma unroll
    for (int p = 0; p < 16; p++) {
        int idx = p * 128 + tid;
        int row = idx >> 5;
        int c16 = idx & 31;
        CP16(ks_a + (uint32_t)(row * SKA + c16 * 4) * 4,
             Qg + (size_t)row * DMODEL + c16 * 4);
    }
    CP_COMMIT(); CP_WAIT0();
    __syncthreads();

    uint32_t qa[16][4];
#pragma unroll
    for (int kc = 0; kc < 16; kc++) {
        const float* rp = Ks + (w * 16 + gr) * SKA + kc * 8 + tg;
        qa[kc][0] = __float_as_uint(rp[0]);
        qa[kc][1] = __float_as_uint(rp[8 * SKA]);
        qa[kc][2] = __float_as_uint(rp[4]);
        qa[kc][3] = __float_as_uint(rp[8 * SKA + 4]);
    }
    __syncthreads();

    float m0 = -1e30f, m1 = -1e30f, l0 = 0.0f, l1 = 0.0f;
    float co[16][4];
#pragma unroll
    for (int jb = 0; jb < 16; jb++)
#pragma unroll
        for (int e = 0; e < 4; e++) co[jb][e] = 0.0f;

    const int r0loc = w * 16 + gr;
    const int r1loc = r0loc + 8;

    const int nkt = qt + 1;
    for (int kt = 0; kt < nkt; kt++) {
        // ---- K group, then V group (V completes while S is computed) ----
#pragma unroll
        for (int p = 0; p < 8; p++) {
            int idx = p * 128 + tid;
            int row = idx >> 4;
            int c16 = idx & 15;
            CP16(ks_a + (uint32_t)(row * SKA + c16 * 8) * 4,
                 Kg + (size_t)(kt * 64 + row) * KV_D + c16 * 8);
            CP16(ks_a + (uint32_t)(row * SKA + c16 * 8 + 4) * 4,
                 Kg + (size_t)(kt * 64 + row) * KV_D + c16 * 8 + 4);
        }
        CP_COMMIT();
#pragma unroll
        for (int p = 0; p < 16; p++) {
            int idx = p * 128 + tid;
            int row = idx >> 5;
            int c16 = idx & 31;
            CP16(vs_a + (uint32_t)(row * SVA + c16 * 4) * 4,
                 Vg + (size_t)(kt * 64 + row) * KV_D + c16 * 4);
        }
        CP_COMMIT();
        CP_WAIT1();             // K ready; V still in flight
        __syncthreads();

        // ---- S = Q @ K^T ----
        float sacc[8][4];
#pragma unroll
        for (int nb = 0; nb < 8; nb++)
#pragma unroll
            for (int e = 0; e < 4; e++) sacc[nb][e] = 0.0f;

#pragma unroll
        for (int kc = 0; kc < 16; kc++) {
            uint32_t bf[8][2];
#pragma unroll
            for (int nb = 0; nb < 8; nb++) {
                const float* bp = Ks + (nb * 8 + gr) * SKA + kc * 8 + tg;
                bf[nb][0] = __float_as_uint(bp[0]);
                bf[nb][1] = __float_as_uint(bp[4]);
            }
#pragma unroll
            for (int nb = 0; nb < 8; nb++)
                mma_tf32(sacc[nb], qa[kc], bf[nb]);
        }

        // ---- softcap + causal mask ----
        const bool diag = (kt == qt);
#pragma unroll
        for (int nb = 0; nb < 8; nb++) {
#pragma unroll
            for (int e = 0; e < 4; e++) {
                float v = sacc[nb][e];
                float t = __expf(2.0f * v);
                float sc = __fdividef(t - 1.0f, t + 1.0f) * 50.0f;
                if (diag) {
                    int cloc = nb * 8 + 2 * tg + (e & 1);
                    int rloc = (e < 2) ? r0loc : r1loc;
                    if (cloc > rloc) sc = -1e30f;
                }
                sacc[nb][e] = sc;
            }
        }

        // ---- online softmax ----
        float rm0 = -1e30f, rm1 = -1e30f;
#pragma unroll
        for (int nb = 0; nb < 8; nb++) {
            rm0 = fmaxf(rm0, fmaxf(sacc[nb][0], sacc[nb][1]));
            rm1 = fmaxf(rm1, fmaxf(sacc[nb][2], sacc[nb][3]));
        }
#pragma unroll
        for (int off = 1; off <= 2; off <<= 1) {
            rm0 = fmaxf(rm0, __shfl_xor_sync(0xffffffffu, rm0, off));
            rm1 = fmaxf(rm1, __shfl_xor_sync(0xffffffffu, rm1, off));
        }
        const float mn0 = fmaxf(m0, rm0);
        const float mn1 = fmaxf(m1, rm1);

        float rs0 = 0.0f, rs1 = 0.0f;
#pragma unroll
        for (int nb = 0; nb < 8; nb++) {
            float p00 = to_tf32(__expf(sacc[nb][0] - mn0));
            float p01 = to_tf32(__expf(sacc[nb][1] - mn0));
            float p10 = to_tf32(__expf(sacc[nb][2] - mn1));
            float p11 = to_tf32(__expf(sacc[nb][3] - mn1));
            rs0 += p00 + p01;
            rs1 += p10 + p11;
            *(float2*)&Ps[r0loc * SPA + nb * 8 + 2 * tg] = make_float2(p00, p01);
            *(float2*)&Ps[r1loc * SPA + nb * 8 + 2 * tg] = make_float2(p10, p11);
        }
#pragma unroll
        for (int off = 1; off <= 2; off <<= 1) {
            rs0 += __shfl_xor_sync(0xffffffffu, rs0, off);
            rs1 += __shfl_xor_sync(0xffffffffu, rs1, off);
        }
        const float a0 = __expf(m0 - mn0);
        const float a1 = __expf(m1 - mn1);
        l0 = l0 * a0 + rs0;  m0 = mn0;
        l1 = l1 * a1 + rs1;  m1 = mn1;
#pragma unroll
        for (int jb = 0; jb < 16; jb++) {
            co[jb][0] *= a0; co[jb][1] *= a0;
            co[jb][2] *= a1; co[jb][3] *= a1;
        }

        CP_WAIT0();             // V ready
        __syncthreads();        // V visible across warps (P is warp-local)

        // ---- O += P @ V ----
#pragma unroll
        for (int kc = 0; kc < 8; kc++) {
            uint32_t pa[4];
            const float* pp = Ps + r0loc * SPA + kc * 8 + tg;
            pa[0] = __float_as_uint(pp[0]);
            pa[1] = __float_as_uint(pp[8 * SPA]);
            pa[2] = __float_as_uint(pp[4]);
            pa[3] = __float_as_uint(pp[8 * SPA + 4]);
#pragma unroll
            for (int jb = 0; jb < 16; jb++) {
                uint32_t bv[2];
                const float* vp = Vs + (kc * 8 + tg) * SVA + jb * 8 + gr;
                bv[0] = __float_as_uint(vp[0]);
                bv[1] = __float_as_uint(vp[4 * SVA]);
                mma_tf32(co[jb], pa, bv);
            }
        }
        __syncthreads();
    }

    // ---- normalize + RN-tf32 + write out ----
    const float inv0 = 1.0f / l0;
    const float inv1 = 1.0f / l1;
    const int rowg0 = bb * SEQ + qt * 64 + r0loc;
    float* op0 = g_att + (size_t)rowg0 * DMODEL + h * HD;
    float* op1 = g_att + (size_t)(rowg0 + 8) * DMODEL + h * HD;
#pragma unroll
    for (int jb = 0; jb < 16; jb++) {
        int col = jb * 8 + 2 * tg;
        *(float2*)(op0 + col) = make_float2(to_tf32(co[jb][0] * inv0),
                                            to_tf32(co[jb][1] * inv0));
        *(float2*)(op1 + col) = make_float2(to_tf32(co[jb][2] * inv1),
                                            to_tf32(co[jb][3] * inv1));
    }
}

// ---------------------------------------------------------------------------
extern "C" void kernel_launch(void* const* d_in, const int* in_sizes, int n_in,
                              void* d_out, int out_size)
{
    const float* x  = (const float*)d_in[0];
    const float* wq = (const float*)d_in[1];
    const float* wk = (const float*)d_in[2];
    const float* wv = (const float*)d_in[3];
    const float* wo = (const float*)d_in[4];
    float* out = (float*)d_out;

    float *xc, *wqc, *wkc, *wvc, *woc;
    cudaGetSymbolAddress((void**)&xc,  g_xc);
    cudaGetSymbolAddress((void**)&wqc, g_wqc);
    cudaGetSymbolAddress((void**)&wkc, g_wkc);
    cudaGetSymbolAddress((void**)&wvc, g_wvc);
    cudaGetSymbolAddress((void**)&woc, g_woc);

    cudaFuncSetAttribute(gemm_qkv,
                         cudaFuncAttributeMaxDynamicSharedMemorySize, GEMM_SMEM_BYTES);
    cudaFuncSetAttribute(gemm_o,
                         cudaFuncAttributeMaxDynamicSharedMemorySize, GEMM_SMEM_BYTES);
    cudaFuncSetAttribute(attn_mma_kernel,
                         cudaFuncAttributeMaxDynamicSharedMemorySize, ATT2_SMEM_BYTES);

    // tf32 round-to-nearest copies of GEMM inputs
    const int n4_x  = M_ROWS * DMODEL / 4;
    const int n4_wq = DMODEL * DMODEL / 4;
    const int n4_wk = KV_D   * DMODEL / 4;
    cvt_tf32_kernel<<<(n4_x  + 255)/256, 256>>>(x,  xc,  n4_x);
    cvt_tf32_kernel<<<(n4_wq + 255)/256, 256>>>(wq, wqc, n4_wq);
    cvt_tf32_kernel<<<(n4_wk + 255)/256, 256>>>(wk, wkc, n4_wk);
    cvt_tf32_kernel<<<(n4_wk + 255)/256, 256>>>(wv, wvc, n4_wk);
    cvt_tf32_kernel<<<(n4_wq + 255)/256, 256>>>(wo, woc, n4_wq);

    // Fused QKV projections (V output tf32-rounded in epilogue)
    gemm_qkv<<<dim3(32, M_ROWS/BM), 256, GEMM_SMEM_BYTES>>>(xc, wqc, wkc, wvc);

    // RoPE (emits tf32-rounded Q(scaled)/K)
    rope_kernel<<<(M_ROWS * (NH + NKV) * 64) / 256, 256>>>();

    // Tensor-core flash attention (emits tf32-rounded output)
    attn_mma_kernel<<<dim3(SEQ/64, NH, BATCH), 128, ATT2_SMEM_BYTES>>>();

    // Output projection
    gemm_o<<<dim3(DMODEL/BN, M_ROWS/BM), 256, GEMM_SMEM_BYTES>>>(woc, out);
}